// round 17
// baseline (speedup 1.0000x reference)
#include <cuda_runtime.h>

#define THREADS 256
#define NBINS 16
#define MAXGRID 740          // 5 persistent blocks per SM on 148 SMs

__device__ float g_partials[32768];
__device__ unsigned int g_counter = 0;

__device__ __forceinline__ void cp_async16(void* smem_dst, const void* gsrc) {
    unsigned saddr = (unsigned)__cvta_generic_to_shared(smem_dst);
    asm volatile("cp.async.cg.shared.global [%0], [%1], 16;"
                 :: "r"(saddr), "l"(gsrc));
}
__device__ __forceinline__ void cp_async_commit() {
    asm volatile("cp.async.commit_group;");
}
template <int N>
__device__ __forceinline__ void cp_async_wait() {
    asm volatile("cp.async.wait_group %0;" :: "n"(N));
}

// Scalar fallback for tail dims (unused when dim % 256 == 0).
__device__ float ep_scalar_dim(const float* __restrict__ obs,
                               const float* __restrict__ counts,
                               float* __restrict__ out,
                               int dim, int rows, float inv_rows, int i)
{
    float m = 0.0f;
    for (int r = 0; r < rows; ++r) m += obs[(size_t)r * dim + i];
    m *= inv_rows;
    float sgm = 1.0f / (1.0f + __expf(-m));
    int b = (int)(sgm * (float)(NBINS - 1));
    b = b < 0 ? 0 : (b > NBINS - 1 ? NBINS - 1 : b);

    float c[NBINS];
    #pragma unroll
    for (int j = 0; j < NBINS; ++j) c[j] = counts[(size_t)i * NBINS + j];
    float s = 0.0f;
    #pragma unroll
    for (int j = 0; j < NBINS; ++j) s += c[j];
    float inv  = 1.0f / fmaxf(s,        1e-8f);
    float invp = 1.0f / fmaxf(s + 1.0f, 1e-8f);
    float Hp = 0.0f, Hq = 0.0f, ig = 0.0f;
    #pragma unroll
    for (int j = 0; j < NBINS; ++j) {
        float oh = (j == b) ? 1.0f : 0.0f;
        float p  = c[j] * inv;
        float pp = (c[j] + oh) * invp;
        float lp = __log2f(p  + 1e-10f);
        float lq = __log2f(pp + 1e-10f);
        Hp -= p * lp; Hq -= pp * lq;
        ig += pp * (lq - lp);
        out[(size_t)3 * dim + 2 + (size_t)i * NBINS + j] =
            fmaxf(c[j] * 0.95f + oh * 0.05f, 0.01f);
    }
    ig = fmaxf(ig, 0.0f);
    out[i] = ig;
    out[(size_t)dim     + 1 + i] = Hp;
    out[(size_t)2 * dim + 1 + i] = Hq;
    return ig;
}

__global__ void __launch_bounds__(THREADS, 5) ep_pipe_kernel(
    const float* __restrict__ obs,      // (rows, dim)
    const float* __restrict__ counts,   // (dim, 16)
    float* __restrict__ out,            // concatenated outputs
    int dim, int rows, float inv_rows, int nblocks, int ntiles)
{
    // Double-buffered padded staging: dim d owns float4 slots [d*5, d*5+4);
    // slot d*5+4 is padding (conflict-free LDS.128 per-row reads).
    __shared__ float4 s4[2][THREADS * 5];   // 40 KB
    __shared__ int    sb[2][THREADS];

    const int t = threadIdx.x;
    float igacc = 0.0f;

    int tile = blockIdx.x;
    const int step = gridDim.x;

    // Issue counts tile -> s4[buf] via cp.async (no registers consumed).
    auto issue_counts = [&](int tl, int buf) {
        const float4* cin = (const float4*)counts + (size_t)tl * THREADS * 4;
        #pragma unroll
        for (int k = 0; k < 4; ++k) {
            int idx = t + k * THREADS;
            cp_async16(&s4[buf][(idx >> 2) * 5 + (idx & 3)], cin + idx);
        }
        cp_async_commit();
    };

    float o0, o1, o2, o3, o4, o5, o6, o7;   // obs pipeline regs

    auto issue_obs = [&](int tl) {
        const float* op = obs + tl * THREADS + t;
        if (rows == 8) {
            o0 = __ldcs(op);
            o1 = __ldcs(op + (size_t)dim);
            o2 = __ldcs(op + (size_t)2 * dim);
            o3 = __ldcs(op + (size_t)3 * dim);
            o4 = __ldcs(op + (size_t)4 * dim);
            o5 = __ldcs(op + (size_t)5 * dim);
            o6 = __ldcs(op + (size_t)6 * dim);
            o7 = __ldcs(op + (size_t)7 * dim);
        } else {
            o0 = 0.0f;
            for (int r = 0; r < rows; ++r) o0 += __ldcs(op + (size_t)r * dim);
            o1 = o2 = o3 = o4 = o5 = o6 = o7 = 0.0f;
        }
    };

    auto bin_to_sb = [&](int buf) {
        float m = (((o0 + o1) + (o2 + o3)) + ((o4 + o5) + (o6 + o7))) * inv_rows;
        float sgm = 1.0f / (1.0f + __expf(-m));
        int b = (int)(sgm * (float)(NBINS - 1));
        b = b < 0 ? 0 : (b > NBINS - 1 ? NBINS - 1 : b);
        sb[buf][t] = b;
    };

    // ---------------- prologue: tile0 in flight ----------------
    if (tile < ntiles) {
        issue_obs(tile);
        issue_counts(tile, 0);
        bin_to_sb(0);            // stalls on obs loads (prologue only)
    }

    // ---------------- pipelined main loop ----------------
    int cur = 0;
    while (tile < ntiles) {
        const int next_tile = tile + step;
        const bool have_next = (next_tile < ntiles);

        // 1) issue next tile's loads (background copies + obs regs).
        //    Writing s4[1-cur] here is safe: every thread passed the END
        //    barrier of the previous iteration after its last read of that
        //    buffer.
        if (have_next) {
            issue_obs(next_tile);
            issue_counts(next_tile, 1 - cur);
            cp_async_wait<1>();      // counts for CURRENT tile complete
        } else {
            cp_async_wait<0>();
        }
        __syncthreads();             // copies + sb[cur] visible block-wide

        // 2) compute + store current tile from smem[cur]
        {
            const int base = tile * THREADS;
            const int i = base + t;
            const int b = sb[cur][t];

            float c[NBINS];
            #pragma unroll
            for (int q = 0; q < 4; ++q) {
                float4 v = s4[cur][t * 5 + q];
                c[4*q+0] = v.x; c[4*q+1] = v.y; c[4*q+2] = v.z; c[4*q+3] = v.w;
            }

            float s = 0.0f;
            #pragma unroll
            for (int j = 0; j < NBINS; ++j) s += c[j];

            // log2(c/s + 1e-10) = log2(c + 1e-10*s) - log2(s)  (exact)
            const float tiny = 1e-10f * s;
            float T = 0.0f, cb = 0.0f, ubin = 0.0f;
            #pragma unroll
            for (int j = 0; j < NBINS; ++j) {
                float u = __log2f(c[j] + tiny);
                T += c[j] * u;
                if (j == b) { cb = c[j]; ubin = u; }
            }
            float ub  = __log2f(cb + 1.0f);
            float ls  = __log2f(s);
            float ls1 = __log2f(s + 1.0f);
            float inv  = 1.0f / s;
            float invp = 1.0f / (s + 1.0f);

            float Hp = ls  - T * inv;
            float Hq = ls1 - (T - cb * ubin + (cb + 1.0f) * ub) * invp;
            float ig = fmaxf((cb + 1.0f) * invp * (ub - ubin) - (ls1 - ls), 0.0f);

            __stcs(out + i, ig);
            __stcs(out + (size_t)dim     + 1 + i, Hp);
            __stcs(out + (size_t)2 * dim + 1 + i, Hq);
            igacc += ig;

            // coalesced new_counts stage-out (2048 float2 slots)
            const float2* s2 = (const float2*)s4[cur];
            float2* obase = (float2*)(out + (size_t)3 * dim + 2 + (size_t)base * NBINS);
            #pragma unroll
            for (int k = 0; k < 8; ++k) {
                int idx = t + k * THREADS;
                int d = idx >> 3, h = idx & 7;
                float2 cc = s2[d * 10 + h];
                int bd = sb[cur][d];
                float w0 = (2 * h     == bd) ? 0.05f : 0.0f;
                float w1 = (2 * h + 1 == bd) ? 0.05f : 0.0f;
                float2 r;
                r.x = fmaxf(cc.x * 0.95f + w0, 0.01f);
                r.y = fmaxf(cc.y * 0.95f + w1, 0.01f);
                __stcs(obase + idx, r);
            }
        }

        // 3) bin for next tile (obs loads drained during compute)
        if (have_next) bin_to_sb(1 - cur);

        // END barrier: all threads done reading s4[cur]/sb[cur] before any
        // thread's next-iteration cp.async may overwrite that buffer.
        __syncthreads();

        tile = next_tile;
        cur ^= 1;
    }

    // ---------------- scalar tail dims (dim % 256 != 0) ----------------
    for (int i = ntiles * THREADS + blockIdx.x * THREADS + t; i < dim;
         i += gridDim.x * THREADS)
        igacc += ep_scalar_dim(obs, counts, out, dim, rows, inv_rows, i);

    // ---------------- deterministic block reduction ----------------
    const unsigned FULL_M = 0xffffffffu;
    #pragma unroll
    for (int o = 16; o > 0; o >>= 1)
        igacc += __shfl_down_sync(FULL_M, igacc, o);

    __shared__ float ws[THREADS / 32];
    int lane = t & 31;
    int w    = t >> 5;
    if (lane == 0) ws[w] = igacc;
    __syncthreads();
    if (w == 0) {
        float v = (lane < THREADS / 32) ? ws[lane] : 0.0f;
        #pragma unroll
        for (int o = 4; o > 0; o >>= 1)
            v += __shfl_down_sync(FULL_M, v, o);
        if (lane == 0) g_partials[blockIdx.x] = v;
    }

    // ---------------- last-block final reduction ----------------
    __shared__ bool is_last;
    __threadfence();
    if (t == 0) {
        unsigned ticket = atomicAdd(&g_counter, 1u);
        is_last = (ticket == (unsigned)(nblocks - 1));
    }
    __syncthreads();

    if (is_last) {
        __threadfence();
        __shared__ double sh[THREADS];
        double a = 0.0;
        for (int p = t; p < nblocks; p += THREADS)   // fixed order
            a += (double)g_partials[p];
        sh[t] = a;
        __syncthreads();
        #pragma unroll
        for (int o = THREADS / 2; o > 0; o >>= 1) {
            if (t < o) sh[t] += sh[t + o];
            __syncthreads();
        }
        if (t == 0) {
            float mean = (float)(sh[0] / (double)dim);
            out[dim] = mean;
            float z = mean * 50.0f - 1.0f;
            out[(size_t)3 * dim + 1] = 1.0f / (1.0f + expf(-z));
            g_counter = 0;   // reset for next graph replay
        }
    }
}

extern "C" void kernel_launch(void* const* d_in, const int* in_sizes, int n_in,
                              void* d_out, int out_size)
{
    const float* obs    = (const float*)d_in[0];
    const float* counts = (const float*)d_in[1];
    float* out = (float*)d_out;

    int dim    = in_sizes[1] / NBINS;
    int rows   = in_sizes[0] / dim;
    int ntiles = dim / THREADS;                 // full tiles only
    int nb     = ntiles < 1 ? 1 : (ntiles < MAXGRID ? ntiles : MAXGRID);

    ep_pipe_kernel<<<nb, THREADS>>>(obs, counts, out, dim, rows,
                                    1.0f / (float)rows, nb, ntiles);
}